// round 3
// baseline (speedup 1.0000x reference)
#include <cuda_runtime.h>
#include <math.h>
#include <stdint.h>

#define TOK   1024   // B*S
#define SLEN  256
#define BATCH 4
#define HID   512
#define DINP  1024
#define GHID  2048
#define NPRE  4096   // 2 dirs * 4H

#define NBLK     64      // blocks per direction in lstm kernel
#define NBLK_TOT 128
#define WT_STRIDE 33

typedef unsigned long long ull;

// ---------------- device scratch (static, no allocation) ----------------
__device__ float g_xA[TOK * DINP];
__device__ float g_xB[TOK * DINP];
__device__ float g_pre[TOK * NPRE];
__device__ float g_pa[TOK * HID];
__device__ float g_pb[TOK * HID];
__device__ float    g_hseq[2 * SLEN * NBLK * 32];   // [dir][step][blk][j*4+b]
__device__ unsigned g_tag [2 * SLEN * NBLK];        // release tags

// ---------------- helpers ----------------
__device__ __forceinline__ float sigf(float x) {
    return 1.0f / (1.0f + __expf(-x));
}
__device__ __forceinline__ float tanh_acc(float x) {
    x = fminf(fmaxf(x, -30.0f), 30.0f);
    float e = __expf(-2.0f * x);
    return (1.0f - e) / (1.0f + e);
}
__device__ __forceinline__ float tanh_fast(float x) {
    float y;
    asm("tanh.approx.f32 %0, %1;" : "=f"(y) : "f"(x));
    return y;
}
__device__ __forceinline__ ull pk2(float x) {
    ull d; asm("mov.b64 %0, {%1, %1};" : "=l"(d) : "f"(x)); return d;
}
__device__ __forceinline__ void fma2(ull& acc, ull a, ull b) {
    asm("fma.rn.f32x2 %0, %1, %2, %0;" : "+l"(acc) : "l"(a), "l"(b));
}
__device__ __forceinline__ float lo2(ull v) { return __uint_as_float((unsigned)v); }
__device__ __forceinline__ float hi2(ull v) { return __uint_as_float((unsigned)(v >> 32)); }
__device__ __forceinline__ unsigned ld_acq(const unsigned* p) {
    unsigned v;
    asm volatile("ld.acquire.gpu.global.b32 %0, [%1];" : "=r"(v) : "l"(p));
    return v;
}
__device__ __forceinline__ void st_rel(unsigned* p, unsigned v) {
    asm volatile("st.release.gpu.global.b32 [%0], %1;" :: "l"(p), "r"(v));
}

__global__ void zero_tags_kernel() {
    g_tag[blockIdx.x * 256 + threadIdx.x] = 0u;
}

// ---------------- embedding gather + concat ----------------
__global__ __launch_bounds__(256) void embed_kernel(
    const int* __restrict__ sent, const int* __restrict__ pos,
    const float* __restrict__ emb)
{
    int gid = blockIdx.x * 256 + threadIdx.x;   // over TOK*256 float4s
    int token = gid >> 8;
    int q = gid & 255;
    const float4* src;
    if (q < 128) src = (const float4*)(emb + (size_t)sent[token] * HID) + q;
    else         src = (const float4*)(emb + (size_t)pos[token]  * HID) + (q - 128);
    ((float4*)g_xA)[gid] = *src;
}

// ---------------- fp32x2 SIMT GEMM: C[M,N] = A[M,K] * B[N,K]^T + bias(n) ----------------
// block tile 128x128, BK=16, 256 threads, 8x8 per thread via packed fma.rn.f32x2.
__global__ __launch_bounds__(256) void gemm_kernel(
    const float* __restrict__ A, const float* __restrict__ B,
    float* __restrict__ C, int N, int K, int ldb,
    const float* __restrict__ bias1, const float* __restrict__ bias2)
{
    __shared__ float As[16][128];
    __shared__ float Bs[16][128];
    const int tid = threadIdx.x;
    const int bm = blockIdx.y << 7, bn = blockIdx.x << 7;
    const int row = tid >> 1;          // 0..127
    const int kq  = (tid & 1) << 3;    // 0 or 8
    const int tx = tid & 15, ty = tid >> 4;
    const int n0 = tx << 2, m0 = ty << 2;

    const float* Ap = A + (size_t)(bm + row) * K + kq;
    const float* Bp = B + (size_t)(bn + row) * ldb + kq;

    ull acc[8][4];
#pragma unroll
    for (int i = 0; i < 8; i++)
#pragma unroll
        for (int j = 0; j < 4; j++) acc[i][j] = 0ull;

    float4 a0v = *(const float4*)(Ap);
    float4 a1v = *(const float4*)(Ap + 4);
    float4 b0v = *(const float4*)(Bp);
    float4 b1v = *(const float4*)(Bp + 4);

    for (int k0 = 0; k0 < K; k0 += 16) {
        As[kq + 0][row] = a0v.x; As[kq + 1][row] = a0v.y;
        As[kq + 2][row] = a0v.z; As[kq + 3][row] = a0v.w;
        As[kq + 4][row] = a1v.x; As[kq + 5][row] = a1v.y;
        As[kq + 6][row] = a1v.z; As[kq + 7][row] = a1v.w;
        Bs[kq + 0][row] = b0v.x; Bs[kq + 1][row] = b0v.y;
        Bs[kq + 2][row] = b0v.z; Bs[kq + 3][row] = b0v.w;
        Bs[kq + 4][row] = b1v.x; Bs[kq + 5][row] = b1v.y;
        Bs[kq + 6][row] = b1v.z; Bs[kq + 7][row] = b1v.w;
        __syncthreads();

        if (k0 + 16 < K) {
            a0v = *(const float4*)(Ap + k0 + 16);
            a1v = *(const float4*)(Ap + k0 + 20);
            b0v = *(const float4*)(Bp + k0 + 16);
            b1v = *(const float4*)(Bp + k0 + 20);
        }

#pragma unroll
        for (int k = 0; k < 16; k++) {
            float4 am0 = *(const float4*)&As[k][m0];
            float4 am1 = *(const float4*)&As[k][m0 + 64];
            ulonglong2 bb0 = *(const ulonglong2*)&Bs[k][n0];
            ulonglong2 bb1 = *(const ulonglong2*)&Bs[k][n0 + 64];
            ull ad[8];
            ad[0] = pk2(am0.x); ad[1] = pk2(am0.y); ad[2] = pk2(am0.z); ad[3] = pk2(am0.w);
            ad[4] = pk2(am1.x); ad[5] = pk2(am1.y); ad[6] = pk2(am1.z); ad[7] = pk2(am1.w);
#pragma unroll
            for (int i = 0; i < 8; i++) {
                fma2(acc[i][0], ad[i], bb0.x);
                fma2(acc[i][1], ad[i], bb0.y);
                fma2(acc[i][2], ad[i], bb1.x);
                fma2(acc[i][3], ad[i], bb1.y);
            }
        }
        __syncthreads();
    }

    // bias per n (8 columns this thread touches)
    float bz[8];
#pragma unroll
    for (int jj = 0; jj < 8; jj++) {
        int n = bn + n0 + ((jj < 4) ? jj : 60 + jj);   // n0+{0,1,2,3}, n0+64+{0..3}
        float bb = 0.0f;
        if (bias1) bb += bias1[n];
        if (bias2) bb += bias2[n];
        bz[jj] = bb;
    }
#pragma unroll
    for (int i = 0; i < 8; i++) {
        int m = bm + m0 + ((i < 4) ? i : 60 + i);      // m0+{0..3}, m0+64+{0..3}
        float* Cr = C + (size_t)m * N + bn + n0;
        Cr[0]  = lo2(acc[i][0]) + bz[0];
        Cr[1]  = hi2(acc[i][0]) + bz[1];
        Cr[2]  = lo2(acc[i][1]) + bz[2];
        Cr[3]  = hi2(acc[i][1]) + bz[3];
        Cr[64] = lo2(acc[i][2]) + bz[4];
        Cr[65] = hi2(acc[i][2]) + bz[5];
        Cr[66] = lo2(acc[i][3]) + bz[6];
        Cr[67] = hi2(acc[i][3]) + bz[7];
    }
}

// ---------------- persistent bidirectional LSTM scan, dataflow-synced ----------------
// grid = 128 blocks: [0,64) fwd, [64,128) bwd. Each block owns 8 hidden units.
// Per step each block publishes one 128B line (8 units x 4 batch) + release tag;
// consumers spin on acquire tags. No grid barrier.
__global__ __launch_bounds__(256) void lstm_kernel(
    const float* __restrict__ pre,     // [TOK][4096], bias folded
    const float* __restrict__ whh,     // [2][2048][512] this layer
    const int* __restrict__ length,
    float* __restrict__ xout,          // [TOK][1024]
    int ltagbase)                      // l*SLEN + 1
{
    extern __shared__ float sm[];
    float*  Wt   = sm;                                  // 512*33
    float4* hbuf = (float4*)(sm + 512 * WT_STRIDE);     // 512 float4
    float*  red  = (float*)(hbuf + 512);                // 1024
    float*  gsum = red + 1024;                          // 128

    const int tid = threadIdx.x;
    const int d   = blockIdx.x / NBLK;
    const int blk = blockIdx.x % NBLK;
    const int u0  = blk * 8;

    // load W_hh slice transposed: rows = gate*512 + u0 + j
    const float* wbase = whh + (size_t)d * GHID * HID;
    for (int idx = tid; idx < 32 * 512; idx += 256) {
        int r = idx >> 9;
        int k = idx & 511;
        int row = ((r >> 3) * HID) + u0 + (r & 7);
        Wt[k * WT_STRIDE + r] = wbase[(size_t)row * HID + k];
    }

    const int r   = tid & 31;
    const int kc  = tid >> 5;
    const int b32 = tid >> 3, j32 = tid & 7;
    const int pp_ = tid >> 2, sub = tid & 3;   // poll mapping: 4 threads per producer

    float creg = 0.0f;
    int len_b = (tid < 32) ? length[b32] : 0;

    unsigned* mytag = g_tag + (d * SLEN) * NBLK + blk;
    float*    myline = g_hseq + ((size_t)(d * SLEN) * NBLK + blk) * 32;

    for (int s = 0; s < SLEN; s++) {
        const int t = d ? (SLEN - 1 - s) : s;

        // prefetch pre-activations for owned gates
        float pi = 0, pf = 0, pg = 0, po = 0;
        if (tid < 32) {
            const float* pp = pre + (size_t)(b32 * SLEN + t) * NPRE + d * GHID + u0 + j32;
            pi = pp[0]; pf = pp[512]; pg = pp[1024]; po = pp[1536];
        }

        // gather h_{s-1} from all 64 producer blocks of this direction
        if (s == 0) {
            hbuf[tid]       = make_float4(0.f, 0.f, 0.f, 0.f);
            hbuf[tid + 256] = make_float4(0.f, 0.f, 0.f, 0.f);
        } else {
            const unsigned* tg = g_tag + (size_t)(d * SLEN + s - 1) * NBLK + pp_;
            const unsigned want = (unsigned)(ltagbase + s - 1);
            while (ld_acq(tg) != want) { }
            const float4* src = (const float4*)(g_hseq +
                ((size_t)(d * SLEN + s - 1) * NBLK + pp_) * 32) + (sub << 1);
            hbuf[pp_ * 8 + sub * 2]     = __ldcg(src);
            hbuf[pp_ * 8 + sub * 2 + 1] = __ldcg(src + 1);
        }
        __syncthreads();

        // stash "hold" value (previous h for my unit) before others can refill hbuf
        float hold = 0.0f;
        if (tid < 32) hold = ((const float*)(hbuf + u0 + j32))[b32];

        // partial matvec, f32x2-packed over batch pairs
        ull acc01 = 0ull, acc23 = 0ull;
        const float* wp  = Wt + (kc * 64) * WT_STRIDE + r;
        const ull*   hp2 = (const ull*)(hbuf + kc * 64);
#pragma unroll 8
        for (int kk = 0; kk < 64; kk++) {
            ull wd = pk2(wp[kk * WT_STRIDE]);
            fma2(acc01, wd, hp2[2 * kk]);
            fma2(acc23, wd, hp2[2 * kk + 1]);
        }
        red[tid]       = lo2(acc01);
        red[256 + tid] = hi2(acc01);
        red[512 + tid] = lo2(acc23);
        red[768 + tid] = hi2(acc23);
        __syncthreads();

        if (tid < 128) {
            int b = tid >> 5, rr = tid & 31;
            float ssum = 0.0f;
#pragma unroll
            for (int q = 0; q < 8; q++) ssum += red[b * 256 + q * 32 + rr];
            gsum[b * 32 + rr] = ssum;
        }
        __syncthreads();

        if (tid < 32) {
            float gi = pi + gsum[b32 * 32 + 0 * 8 + j32];
            float gf = pf + gsum[b32 * 32 + 1 * 8 + j32];
            float gg = pg + gsum[b32 * 32 + 2 * 8 + j32];
            float go = po + gsum[b32 * 32 + 3 * 8 + j32];
            float cn = sigf(gf) * creg + sigf(gi) * tanh_acc(gg);
            float hn = sigf(go) * tanh_acc(cn);
            bool m = (t < len_b);
            if (m) creg = cn;
            float hnew = m ? hn : hold;
            __stcg(myline + (size_t)s * NBLK * 32 + j32 * 4 + b32, hnew);
            xout[(size_t)(b32 * SLEN + t) * DINP + d * HID + u0 + j32] = m ? hn : 0.0f;
            __syncwarp();
            if (tid == 0) {
                __threadfence();
                st_rel(mytag + (size_t)s * NBLK, (unsigned)(ltagbase + s));
            }
        }
        // threads >=32 proceed straight to next step's polling (skew-tolerant)
    }
}

// ---------------- score: out[b,s,t] = b2 + sum_h w2[h]*tanh(pa[b,s,h]+pbb[b,t,h]) ----------------
__global__ __launch_bounds__(256) void score_kernel(
    const float* __restrict__ pa, const float* __restrict__ pb,
    const float* __restrict__ w2, const float* __restrict__ b2,
    float* __restrict__ out)
{
    extern __shared__ float sm[];
    float* paT = sm;                 // [512][17]
    float* pbT = sm + 512 * 17;
    float* w2s = pbT + 512 * 17;     // [512]

    const int tid = threadIdx.x;
    const int btt = blockIdx.x, bss = blockIdx.y, b = blockIdx.z;

    for (int idx = tid; idx < 16 * 512; idx += 256) {
        int row = idx >> 9, h = idx & 511;
        paT[h * 17 + row] = pa[(size_t)(b * SLEN + bss * 16 + row) * HID + h];
        pbT[h * 17 + row] = pb[(size_t)(b * SLEN + btt * 16 + row) * HID + h];
    }
    for (int idx = tid; idx < 512; idx += 256) w2s[idx] = w2[idx];
    __syncthreads();

    const int si = tid & 15, ti = tid >> 4;
    float acc = 0.0f;
#pragma unroll 8
    for (int h = 0; h < 512; h++) {
        float x = paT[h * 17 + si] + pbT[h * 17 + ti];
        acc = fmaf(w2s[h], tanh_fast(x), acc);
    }
    out[(size_t)(b * SLEN + bss * 16 + si) * SLEN + btt * 16 + ti] = acc + b2[0];
}

// ---------------- launch ----------------
extern "C" void kernel_launch(void* const* d_in, const int* in_sizes, int n_in,
                              void* d_out, int out_size)
{
    const int*   sent   = (const int*)d_in[0];
    const int*   pos    = (const int*)d_in[1];
    const int*   length = (const int*)d_in[2];
    const float* emb    = (const float*)d_in[3];
    const float* w_ih   = (const float*)d_in[4];
    const float* w_hh   = (const float*)d_in[5];
    const float* b_ih   = (const float*)d_in[6];
    const float* b_hh   = (const float*)d_in[7];
    const float* w1     = (const float*)d_in[8];
    const float* b1     = (const float*)d_in[9];
    const float* w2     = (const float*)d_in[10];
    const float* b2     = (const float*)d_in[11];
    float* out = (float*)d_out;

    const int LSTM_SMEM  = 512 * WT_STRIDE * 4 + 512 * 16 + 1024 * 4 + 128 * 4;
    const int SCORE_SMEM = 2 * 512 * 17 * 4 + 512 * 4;

    cudaFuncSetAttribute(lstm_kernel,  cudaFuncAttributeMaxDynamicSharedMemorySize, LSTM_SMEM);
    cudaFuncSetAttribute(score_kernel, cudaFuncAttributeMaxDynamicSharedMemorySize, SCORE_SMEM);

    float *xA, *xB, *prep, *pap, *pbp;
    cudaGetSymbolAddress((void**)&xA,   g_xA);
    cudaGetSymbolAddress((void**)&xB,   g_xB);
    cudaGetSymbolAddress((void**)&prep, g_pre);
    cudaGetSymbolAddress((void**)&pap,  g_pa);
    cudaGetSymbolAddress((void**)&pbp,  g_pb);

    zero_tags_kernel<<<128, 256>>>();
    embed_kernel<<<1024, 256>>>(sent, pos, emb);

    for (int l = 0; l < 2; l++) {
        const float* Ain = l ? xB : xA;
        float* Xout      = l ? xA : xB;
        gemm_kernel<<<dim3(NPRE / 128, TOK / 128), 256>>>(
            Ain, w_ih + (size_t)l * NPRE * DINP, prep,
            NPRE, DINP, DINP, b_ih + l * NPRE, b_hh + l * NPRE);
        lstm_kernel<<<NBLK_TOT, 256, LSTM_SMEM>>>(
            prep, w_hh + (size_t)l * 2 * GHID * HID, length, Xout,
            l * SLEN + 1);
    }

    gemm_kernel<<<dim3(HID / 128, TOK / 128), 256>>>(
        xA, w1,        pap, HID, DINP, 2048, nullptr, nullptr);
    gemm_kernel<<<dim3(HID / 128, TOK / 128), 256>>>(
        xA, w1 + 1024, pbp, HID, DINP, 2048, b1, nullptr);

    score_kernel<<<dim3(16, 16, 4), 256, SCORE_SMEM>>>(pap, pbp, w2, b2, out);
}

// round 4
// speedup vs baseline: 1.7719x; 1.7719x over previous
#include <cuda_runtime.h>
#include <math.h>
#include <stdint.h>

#define TOK   1024   // B*S
#define SLEN  256
#define BATCH 4
#define HID   512
#define DINP  1024
#define GHID  2048
#define NPRE  4096   // 2 dirs * 4H

#define NBLK     64      // blocks per direction in lstm kernel
#define NBLK_TOT 128
#define FLAG_PAD 32      // one 128B line per flag

typedef unsigned long long ull;

// ---------------- device scratch (static, no allocation) ----------------
__device__ float g_xA[TOK * DINP];
__device__ float g_xB[TOK * DINP];
__device__ float g_pre[TOK * NPRE];
__device__ float g_pa[TOK * HID];
__device__ float g_pb[TOK * HID];
__device__ float    g_h[2 * 2 * HID * 4];          // [buf][dir][k][batch]
__device__ unsigned g_flag[NBLK_TOT * FLAG_PAD];   // per-block step counters

// ---------------- helpers ----------------
__device__ __forceinline__ float sigf(float x) {
    return 1.0f / (1.0f + __expf(-x));
}
__device__ __forceinline__ float tanh_acc(float x) {
    x = fminf(fmaxf(x, -30.0f), 30.0f);
    float e = __expf(-2.0f * x);
    return (1.0f - e) / (1.0f + e);
}
__device__ __forceinline__ float tanh_fast(float x) {
    float y;
    asm("tanh.approx.f32 %0, %1;" : "=f"(y) : "f"(x));
    return y;
}
__device__ __forceinline__ ull pk2(float x) {
    ull d; asm("mov.b64 %0, {%1, %1};" : "=l"(d) : "f"(x)); return d;
}
__device__ __forceinline__ void fma2(ull& acc, ull a, ull b) {
    asm("fma.rn.f32x2 %0, %1, %2, %0;" : "+l"(acc) : "l"(a), "l"(b));
}
__device__ __forceinline__ float lo2(ull v) { return __uint_as_float((unsigned)v); }
__device__ __forceinline__ float hi2(ull v) { return __uint_as_float((unsigned)(v >> 32)); }
__device__ __forceinline__ unsigned ld_acq(const unsigned* p) {
    unsigned v;
    asm volatile("ld.acquire.gpu.global.b32 %0, [%1];" : "=r"(v) : "l"(p));
    return v;
}
__device__ __forceinline__ void st_rel(unsigned* p, unsigned v) {
    asm volatile("st.release.gpu.global.b32 [%0], %1;" :: "l"(p), "r"(v));
}

__global__ void zero_flags_kernel() {
    g_flag[blockIdx.x * 256 + threadIdx.x] = 0u;
}

// ---------------- embedding gather + concat ----------------
__global__ __launch_bounds__(256) void embed_kernel(
    const int* __restrict__ sent, const int* __restrict__ pos,
    const float* __restrict__ emb)
{
    int gid = blockIdx.x * 256 + threadIdx.x;   // over TOK*256 float4s
    int token = gid >> 8;
    int q = gid & 255;
    const float4* src;
    if (q < 128) src = (const float4*)(emb + (size_t)sent[token] * HID) + q;
    else         src = (const float4*)(emb + (size_t)pos[token]  * HID) + (q - 128);
    ((float4*)g_xA)[gid] = *src;
}

// ---------------- fp32x2 SIMT GEMM: C[M,N] = A[M,K] * B[N,K]^T + bias(n) ----------------
// block tile 128x128, BK=16, 256 threads, 8x8 per thread via packed fma.rn.f32x2.
__global__ __launch_bounds__(256) void gemm_kernel(
    const float* __restrict__ A, const float* __restrict__ B,
    float* __restrict__ C, int N, int K, int ldb,
    const float* __restrict__ bias1, const float* __restrict__ bias2)
{
    __shared__ float As[16][128];
    __shared__ float Bs[16][128];
    const int tid = threadIdx.x;
    const int bm = blockIdx.y << 7, bn = blockIdx.x << 7;
    const int row = tid >> 1;          // 0..127
    const int kq  = (tid & 1) << 3;    // 0 or 8
    const int tx = tid & 15, ty = tid >> 4;
    const int n0 = tx << 2, m0 = ty << 2;

    const float* Ap = A + (size_t)(bm + row) * K + kq;
    const float* Bp = B + (size_t)(bn + row) * ldb + kq;

    ull acc[8][4];
#pragma unroll
    for (int i = 0; i < 8; i++)
#pragma unroll
        for (int j = 0; j < 4; j++) acc[i][j] = 0ull;

    float4 a0v = *(const float4*)(Ap);
    float4 a1v = *(const float4*)(Ap + 4);
    float4 b0v = *(const float4*)(Bp);
    float4 b1v = *(const float4*)(Bp + 4);

    for (int k0 = 0; k0 < K; k0 += 16) {
        As[kq + 0][row] = a0v.x; As[kq + 1][row] = a0v.y;
        As[kq + 2][row] = a0v.z; As[kq + 3][row] = a0v.w;
        As[kq + 4][row] = a1v.x; As[kq + 5][row] = a1v.y;
        As[kq + 6][row] = a1v.z; As[kq + 7][row] = a1v.w;
        Bs[kq + 0][row] = b0v.x; Bs[kq + 1][row] = b0v.y;
        Bs[kq + 2][row] = b0v.z; Bs[kq + 3][row] = b0v.w;
        Bs[kq + 4][row] = b1v.x; Bs[kq + 5][row] = b1v.y;
        Bs[kq + 6][row] = b1v.z; Bs[kq + 7][row] = b1v.w;
        __syncthreads();

        if (k0 + 16 < K) {
            a0v = *(const float4*)(Ap + k0 + 16);
            a1v = *(const float4*)(Ap + k0 + 20);
            b0v = *(const float4*)(Bp + k0 + 16);
            b1v = *(const float4*)(Bp + k0 + 20);
        }

#pragma unroll
        for (int k = 0; k < 16; k++) {
            float4 am0 = *(const float4*)&As[k][m0];
            float4 am1 = *(const float4*)&As[k][m0 + 64];
            ulonglong2 bb0 = *(const ulonglong2*)&Bs[k][n0];
            ulonglong2 bb1 = *(const ulonglong2*)&Bs[k][n0 + 64];
            ull ad[8];
            ad[0] = pk2(am0.x); ad[1] = pk2(am0.y); ad[2] = pk2(am0.z); ad[3] = pk2(am0.w);
            ad[4] = pk2(am1.x); ad[5] = pk2(am1.y); ad[6] = pk2(am1.z); ad[7] = pk2(am1.w);
#pragma unroll
            for (int i = 0; i < 8; i++) {
                fma2(acc[i][0], ad[i], bb0.x);
                fma2(acc[i][1], ad[i], bb0.y);
                fma2(acc[i][2], ad[i], bb1.x);
                fma2(acc[i][3], ad[i], bb1.y);
            }
        }
        __syncthreads();
    }

    float bz[8];
#pragma unroll
    for (int jj = 0; jj < 8; jj++) {
        int n = bn + n0 + ((jj < 4) ? jj : 60 + jj);
        float bb = 0.0f;
        if (bias1) bb += bias1[n];
        if (bias2) bb += bias2[n];
        bz[jj] = bb;
    }
#pragma unroll
    for (int i = 0; i < 8; i++) {
        int m = bm + m0 + ((i < 4) ? i : 60 + i);
        float* Cr = C + (size_t)m * N + bn + n0;
        Cr[0]  = lo2(acc[i][0]) + bz[0];
        Cr[1]  = hi2(acc[i][0]) + bz[1];
        Cr[2]  = lo2(acc[i][1]) + bz[2];
        Cr[3]  = hi2(acc[i][1]) + bz[3];
        Cr[64] = lo2(acc[i][2]) + bz[4];
        Cr[65] = hi2(acc[i][2]) + bz[5];
        Cr[66] = lo2(acc[i][3]) + bz[6];
        Cr[67] = hi2(acc[i][3]) + bz[7];
    }
}

// ---------------- persistent bidirectional LSTM scan, flag-barrier ----------------
// grid = 128 blocks: [0,64) fwd, [64,128) bwd. Each block owns 8 hidden units
// (32 gate rows). W_hh slice lives in REGISTERS (64 floats/thread).
// Sync: each block release-stores a monotone step counter into its own 128B
// flag line; consumers (2 warps) acquire-poll the 64 same-direction flags and
// gather that producer's 128B h-line immediately after its flag lands.
__global__ __launch_bounds__(256) void lstm_kernel(
    const float* __restrict__ pre,     // [TOK][4096], bias folded
    const float* __restrict__ whh,     // [2][2048][512] this layer
    const int* __restrict__ length,
    float* __restrict__ xout,          // [TOK][1024]
    int base)                          // l*SLEN
{
    __shared__ float4 hbuf[512];       // h[k][4 batch], k-major
    __shared__ float  red[1024];
    __shared__ float  gsum[128];

    const int tid = threadIdx.x;
    const int d   = blockIdx.x >> 6;
    const int blk = blockIdx.x & 63;
    const int u0  = blk * 8;
    const int r   = tid & 31;          // local gate-row 0..31 (gate = r>>3, j = r&7)
    const int kc  = tid >> 5;          // k-chunk 0..7 (64 k each)
    const int b32 = tid >> 3, j32 = tid & 7;

    // register-resident W_hh slice: wreg[kk] = W[gate*512 + u0 + j][kc*64 + kk]
    float wreg[64];
    {
        const float* wp = whh + (size_t)d * GHID * HID
                        + (size_t)((r >> 3) * HID + u0 + (r & 7)) * HID + kc * 64;
#pragma unroll
        for (int kk = 0; kk < 64; kk++) wreg[kk] = wp[kk];
    }

    float creg = 0.0f, hreg = 0.0f;
    const int len_b = (tid < 32) ? length[tid >> 3] : 0;

    unsigned* myflag = &g_flag[blockIdx.x * FLAG_PAD];
    const unsigned* dirflags = &g_flag[(d * NBLK) * FLAG_PAD];

    for (int s = 0; s < SLEN; s++) {
        const int t = d ? (SLEN - 1 - s) : s;

        // prefetch pre-activations for owned gates (independent of h)
        float pi = 0, pf = 0, pg = 0, po = 0;
        if (tid < 32) {
            const float* pp = pre + (size_t)(b32 * SLEN + t) * NPRE + d * GHID + u0 + j32;
            pi = pp[0]; pf = pp[512]; pg = pp[1024]; po = pp[1536];
        }

        // gather h_{s-1}
        if (s == 0) {
            hbuf[tid]       = make_float4(0.f, 0.f, 0.f, 0.f);
            hbuf[tid + 256] = make_float4(0.f, 0.f, 0.f, 0.f);
        } else if (tid < 64) {
            const unsigned want = (unsigned)(base + s);
            const unsigned* fl = dirflags + tid * FLAG_PAD;
            while (ld_acq(fl) < want) { }
            const float4* src = ((const float4*)g_h) + ((s & 1) * 2 + d) * 512 + tid * 8;
            float4* dst = hbuf + tid * 8;
#pragma unroll
            for (int q = 0; q < 8; q++) dst[q] = __ldcg(src + q);
        }
        __syncthreads();   // S1: hbuf ready (also protects hbuf reuse, see flag order)

        // partial matvec: row r over k chunk kc, batch-packed f32x2
        ull a01 = 0ull, a23 = 0ull;
        const ull* hp = (const ull*)(hbuf + kc * 64);
#pragma unroll
        for (int kk = 0; kk < 64; kk++) {
            ull wd = pk2(wreg[kk]);
            fma2(a01, wd, hp[2 * kk]);
            fma2(a23, wd, hp[2 * kk + 1]);
        }
        red[tid]       = lo2(a01);
        red[256 + tid] = hi2(a01);
        red[512 + tid] = lo2(a23);
        red[768 + tid] = hi2(a23);
        __syncthreads();   // S2

        if (tid < 128) {
            int b = tid >> 5, rr = tid & 31;
            float ssum = 0.0f;
#pragma unroll
            for (int q = 0; q < 8; q++) ssum += red[b * 256 + q * 32 + rr];
            gsum[b * 32 + rr] = ssum;
        }
        __syncthreads();   // S3

        if (tid < 32) {
            float gi = pi + gsum[b32 * 32 + 0 * 8 + j32];
            float gf = pf + gsum[b32 * 32 + 1 * 8 + j32];
            float gg = pg + gsum[b32 * 32 + 2 * 8 + j32];
            float go = po + gsum[b32 * 32 + 3 * 8 + j32];
            float cn = sigf(gf) * creg + sigf(gi) * tanh_acc(gg);
            float hn = sigf(go) * tanh_acc(cn);
            bool m = (t < len_b);
            if (m) { creg = cn; hreg = hn; }
            // publish h (buffer (s+1)&1): 32 consecutive floats = one 128B line
            __stcg(&((float*)g_h)[((((s + 1) & 1) * 2 + d) * 512 + u0 + j32) * 4 + b32], hreg);
            xout[(size_t)(b32 * SLEN + t) * DINP + d * HID + u0 + j32] = m ? hn : 0.0f;
            __threadfence();
            __syncwarp();
            if (tid == 0) st_rel(myflag, (unsigned)(base + s + 1));
        }
        // next iteration's hbuf writers (tid<64) wait on own flag >= base+s+1,
        // which transitively orders them after this block's S3 — no extra sync.
    }
}

// ---------------- score: out[b,s,t] = b2 + sum_h w2[h]*tanh(pa[b,s,h]+pbb[b,t,h]) ----------------
__global__ __launch_bounds__(256) void score_kernel(
    const float* __restrict__ pa, const float* __restrict__ pb,
    const float* __restrict__ w2, const float* __restrict__ b2,
    float* __restrict__ out)
{
    extern __shared__ float sm[];
    float* paT = sm;                 // [512][17]
    float* pbT = sm + 512 * 17;
    float* w2s = pbT + 512 * 17;     // [512]

    const int tid = threadIdx.x;
    const int btt = blockIdx.x, bss = blockIdx.y, b = blockIdx.z;

    for (int idx = tid; idx < 16 * 512; idx += 256) {
        int row = idx >> 9, h = idx & 511;
        paT[h * 17 + row] = pa[(size_t)(b * SLEN + bss * 16 + row) * HID + h];
        pbT[h * 17 + row] = pb[(size_t)(b * SLEN + btt * 16 + row) * HID + h];
    }
    for (int idx = tid; idx < 512; idx += 256) w2s[idx] = w2[idx];
    __syncthreads();

    const int si = tid & 15, ti = tid >> 4;
    float acc = 0.0f;
#pragma unroll 8
    for (int h = 0; h < 512; h++) {
        float x = paT[h * 17 + si] + pbT[h * 17 + ti];
        acc = fmaf(w2s[h], tanh_fast(x), acc);
    }
    out[(size_t)(b * SLEN + bss * 16 + si) * SLEN + btt * 16 + ti] = acc + b2[0];
}

// ---------------- launch ----------------
extern "C" void kernel_launch(void* const* d_in, const int* in_sizes, int n_in,
                              void* d_out, int out_size)
{
    const int*   sent   = (const int*)d_in[0];
    const int*   pos    = (const int*)d_in[1];
    const int*   length = (const int*)d_in[2];
    const float* emb    = (const float*)d_in[3];
    const float* w_ih   = (const float*)d_in[4];
    const float* w_hh   = (const float*)d_in[5];
    const float* b_ih   = (const float*)d_in[6];
    const float* b_hh   = (const float*)d_in[7];
    const float* w1     = (const float*)d_in[8];
    const float* b1     = (const float*)d_in[9];
    const float* w2     = (const float*)d_in[10];
    const float* b2     = (const float*)d_in[11];
    float* out = (float*)d_out;

    const int SCORE_SMEM = 2 * 512 * 17 * 4 + 512 * 4;
    cudaFuncSetAttribute(score_kernel, cudaFuncAttributeMaxDynamicSharedMemorySize, SCORE_SMEM);

    float *xA, *xB, *prep, *pap, *pbp;
    cudaGetSymbolAddress((void**)&xA,   g_xA);
    cudaGetSymbolAddress((void**)&xB,   g_xB);
    cudaGetSymbolAddress((void**)&prep, g_pre);
    cudaGetSymbolAddress((void**)&pap,  g_pa);
    cudaGetSymbolAddress((void**)&pbp,  g_pb);

    zero_flags_kernel<<<NBLK_TOT * FLAG_PAD / 256, 256>>>();
    embed_kernel<<<1024, 256>>>(sent, pos, emb);

    for (int l = 0; l < 2; l++) {
        const float* Ain = l ? xB : xA;
        float* Xout      = l ? xA : xB;
        gemm_kernel<<<dim3(NPRE / 128, TOK / 128), 256>>>(
            Ain, w_ih + (size_t)l * NPRE * DINP, prep,
            NPRE, DINP, DINP, b_ih + l * NPRE, b_hh + l * NPRE);
        lstm_kernel<<<NBLK_TOT, 256>>>(
            prep, w_hh + (size_t)l * 2 * GHID * HID, length, Xout, l * SLEN);
    }

    gemm_kernel<<<dim3(HID / 128, TOK / 128), 256>>>(
        xA, w1,        pap, HID, DINP, 2048, nullptr, nullptr);
    gemm_kernel<<<dim3(HID / 128, TOK / 128), 256>>>(
        xA, w1 + 1024, pbp, HID, DINP, 2048, b1, nullptr);

    score_kernel<<<dim3(16, 16, 4), 256, SCORE_SMEM>>>(pap, pbp, w2, b2, out);
}